// round 1
// baseline (speedup 1.0000x reference)
#include <cuda_runtime.h>

#define N_NODES 50000
#define E_EDGES 800000
#define EN_TOT  (E_EDGES + N_NODES)
#define IN_CH   256
#define OUT_CH  64
#define HEADS   4
#define HC      256           // HEADS*OUT_CH
#define BCOLS   320           // 256 (W) + 64 (W_res)
#define NEG_SLOPE 0.2f

// ---------------- device scratch (static globals; no runtime alloc) ----------
__device__ float    g_B[IN_CH * BCOLS];                 // packed [K, 320] = W | W_res
__device__ float    g_out[(size_t)N_NODES * BCOLS];     // per-node: xw (0..255) | x_res (256..319)
__device__ float    g_alog[N_NODES * 8];                // a_src[4] | a_dst[4] per node
__device__ unsigned g_max[N_NODES * HEADS];             // encoded float max
__device__ float    g_den[N_NODES * HEADS];
__device__ float    g_acc[(size_t)N_NODES * HC];        // scatter accumulator [N,H,C]
__device__ int      g_is64;

// ---------------- helpers ----------------------------------------------------
__device__ __forceinline__ unsigned fenc(float f) {
    unsigned u = __float_as_uint(f);
    return (u & 0x80000000u) ? ~u : (u | 0x80000000u);
}
__device__ __forceinline__ float fdec(unsigned k) {
    unsigned u = (k & 0x80000000u) ? (k & 0x7fffffffu) : ~k;
    return __uint_as_float(u);
}
__device__ __forceinline__ int edge_at(const void* ei, int is64, long long idx) {
    return is64 ? (int)((const long long*)ei)[idx] : ((const int*)ei)[idx];
}
__device__ __forceinline__ unsigned long long fma2(unsigned long long a,
                                                   unsigned long long b,
                                                   unsigned long long c) {
    unsigned long long d;
    asm("fma.rn.f32x2 %0, %1, %2, %3;" : "=l"(d) : "l"(a), "l"(b), "l"(c));
    return d;
}
__device__ __forceinline__ unsigned long long dup2(float x) {
    unsigned long long d;
    asm("mov.b64 %0, {%1, %1};" : "=l"(d) : "f"(x));
    return d;
}
__device__ __forceinline__ float2 unpk2(unsigned long long v) {
    float2 r;
    asm("mov.b64 {%0, %1}, %2;" : "=f"(r.x), "=f"(r.y) : "l"(v));
    return r;
}

// ---------------- k_detect: int32 vs int64 edge_index ------------------------
__global__ void k_detect(const unsigned* __restrict__ ei_words) {
    __shared__ unsigned s_or;
    if (threadIdx.x == 0) s_or = 0;
    __syncthreads();
    unsigned v = 0;
    for (int i = threadIdx.x; i < 4096; i += blockDim.x)
        v |= ei_words[2 * i + 1];          // high words of int64 values (< 2^31) are 0
    if (v) atomicOr(&s_or, 1u);
    __syncthreads();
    if (threadIdx.x == 0) g_is64 = (s_or == 0) ? 1 : 0;
}

// ---------------- k_pack: B = [W | W_res] ------------------------------------
__global__ void k_pack(const float* __restrict__ W, const float* __restrict__ Wr) {
    int total = IN_CH * BCOLS;
    for (int i = blockIdx.x * blockDim.x + threadIdx.x; i < total;
         i += gridDim.x * blockDim.x) {
        int k = i / BCOLS, j = i - k * BCOLS;
        g_B[i] = (j < HC) ? W[k * HC + j] : Wr[k * OUT_CH + (j - HC)];
    }
}

// ---------------- k_gemm: g_out[M,320] = X[M,256] @ g_B[256,320] --------------
// 128x64 block tile, BK=16, 256 threads, 8x4 per thread, f32x2 accumulators.
#define BM 128
#define BN 64
#define BK 16
__global__ __launch_bounds__(256) void k_gemm(const float* __restrict__ X) {
    __shared__ float As[BK][BM];     // [k][m]
    __shared__ float Bs[BK][BN];     // [k][n]
    int bm = blockIdx.x * BM;
    int bn = blockIdx.y * BN;
    int tid = threadIdx.x;
    int tx = tid & 15;               // col group (4 cols)
    int ty = tid >> 4;               // row group (8 rows)

    unsigned long long acc[4][4];
#pragma unroll
    for (int i = 0; i < 4; i++)
#pragma unroll
        for (int j = 0; j < 4; j++) acc[i][j] = 0ull;

    for (int k0 = 0; k0 < IN_CH; k0 += BK) {
        // A tile: 128x16, 2 float4 per thread, transposed store
#pragma unroll
        for (int i = 0; i < 2; i++) {
            int v = tid * 2 + i;
            int row = v >> 2;                // 0..127
            int kq = (v & 3) * 4;            // 0,4,8,12
            int gr = bm + row;
            float4 f = make_float4(0.f, 0.f, 0.f, 0.f);
            if (gr < N_NODES)
                f = *(const float4*)(X + (size_t)gr * IN_CH + k0 + kq);
            As[kq + 0][row] = f.x;
            As[kq + 1][row] = f.y;
            As[kq + 2][row] = f.z;
            As[kq + 3][row] = f.w;
        }
        // B tile: 16x64, 1 float4 per thread
        {
            int row = tid >> 4;
            int cq = (tid & 15) * 4;
            *(float4*)&Bs[row][cq] =
                *(const float4*)(g_B + (k0 + row) * BCOLS + bn + cq);
        }
        __syncthreads();
#pragma unroll
        for (int k = 0; k < BK; k++) {
            ulonglong2 av0 = *(const ulonglong2*)&As[k][ty * 8];      // rows 0..3 (2 pairs)
            ulonglong2 av1 = *(const ulonglong2*)&As[k][ty * 8 + 4];  // rows 4..7
            float4 bv = *(const float4*)&Bs[k][tx * 4];
            unsigned long long a2[4] = {av0.x, av0.y, av1.x, av1.y};
            unsigned long long bd[4] = {dup2(bv.x), dup2(bv.y), dup2(bv.z), dup2(bv.w)};
#pragma unroll
            for (int i = 0; i < 4; i++)
#pragma unroll
                for (int j = 0; j < 4; j++)
                    acc[i][j] = fma2(a2[i], bd[j], acc[i][j]);
        }
        __syncthreads();
    }

#pragma unroll
    for (int i = 0; i < 4; i++) {
        int m0 = bm + ty * 8 + i * 2;
#pragma unroll
        for (int j = 0; j < 4; j++) {
            int col = bn + tx * 4 + j;
            float2 v = unpk2(acc[i][j]);
            if (m0 < N_NODES)      g_out[(size_t)m0 * BCOLS + col] = v.x;
            if (m0 + 1 < N_NODES)  g_out[(size_t)(m0 + 1) * BCOLS + col] = v.y;
        }
    }
}

// ---------------- k_logits: per-node attention logits -------------------------
__global__ void k_logits(const float* __restrict__ att_src,
                         const float* __restrict__ att_dst) {
    __shared__ float satt[512];    // [0..255]=att_src, [256..511]=att_dst, layout h*64+c
    for (int i = threadIdx.x; i < 256; i += blockDim.x) {
        satt[i]       = att_src[i];
        satt[256 + i] = att_dst[i];
    }
    __syncthreads();
    int lane = threadIdx.x & 31;
    int wid = (blockIdx.x * blockDim.x + threadIdx.x) >> 5;
    int nwarps = (gridDim.x * blockDim.x) >> 5;
    for (int n = wid; n < N_NODES; n += nwarps) {
        const float* row = g_out + (size_t)n * BCOLS;
#pragma unroll
        for (int h = 0; h < HEADS; h++) {
            float v0 = row[h * 64 + lane];
            float v1 = row[h * 64 + 32 + lane];
            float ps = v0 * satt[h * 64 + lane] + v1 * satt[h * 64 + 32 + lane];
            float pd = v0 * satt[256 + h * 64 + lane] + v1 * satt[256 + h * 64 + 32 + lane];
#pragma unroll
            for (int o = 16; o; o >>= 1) {
                ps += __shfl_xor_sync(0xffffffffu, ps, o);
                pd += __shfl_xor_sync(0xffffffffu, pd, o);
            }
            if (lane == 0) {
                g_alog[n * 8 + h]     = ps;
                g_alog[n * 8 + 4 + h] = pd;
            }
        }
    }
}

// ---------------- k_init: zero accumulators ----------------------------------
__global__ void k_init() {
    long long idx = blockIdx.x * (long long)blockDim.x + threadIdx.x;
    long long stride = (long long)gridDim.x * blockDim.x;
    long long nacc4 = (long long)N_NODES * HC / 4;
    float4 z = make_float4(0.f, 0.f, 0.f, 0.f);
    for (long long i = idx; i < nacc4; i += stride) ((float4*)g_acc)[i] = z;
    for (long long i = idx; i < (long long)N_NODES * HEADS; i += stride) {
        g_max[i] = 0u;            // encodes below any finite float
        g_den[i] = 0.f;
    }
}

// ---------------- k_max: segment max of leaky-relu logits ---------------------
__global__ void k_max(const void* __restrict__ ei) {
    int is64 = g_is64;
    long long total = (long long)EN_TOT * HEADS;
    for (long long i = blockIdx.x * (long long)blockDim.x + threadIdx.x; i < total;
         i += (long long)gridDim.x * blockDim.x) {
        long long e = i >> 2;
        int h = (int)(i & 3);
        int s, d;
        if (e < E_EDGES) {
            s = edge_at(ei, is64, e);
            d = edge_at(ei, is64, E_EDGES + e);
        } else {
            s = d = (int)(e - E_EDGES);
        }
        float a = g_alog[s * 8 + h] + g_alog[d * 8 + 4 + h];
        a = (a > 0.f) ? a : NEG_SLOPE * a;
        atomicMax(&g_max[d * 4 + h], fenc(a));
    }
}

// ---------------- k_sum: segment sum of exp(alpha - max) ----------------------
__global__ void k_sum(const void* __restrict__ ei) {
    int is64 = g_is64;
    long long total = (long long)EN_TOT * HEADS;
    for (long long i = blockIdx.x * (long long)blockDim.x + threadIdx.x; i < total;
         i += (long long)gridDim.x * blockDim.x) {
        long long e = i >> 2;
        int h = (int)(i & 3);
        int s, d;
        if (e < E_EDGES) {
            s = edge_at(ei, is64, e);
            d = edge_at(ei, is64, E_EDGES + e);
        } else {
            s = d = (int)(e - E_EDGES);
        }
        float a = g_alog[s * 8 + h] + g_alog[d * 8 + 4 + h];
        a = (a > 0.f) ? a : NEG_SLOPE * a;
        float ex = __expf(a - fdec(g_max[d * 4 + h]));
        atomicAdd(&g_den[d * 4 + h], ex);
    }
}

// ---------------- k_scatter: warp per edge, red.global.add.v4 -----------------
__global__ void k_scatter(const void* __restrict__ ei) {
    int is64 = g_is64;
    int lane = threadIdx.x & 31;
    long long w = ((long long)blockIdx.x * blockDim.x + threadIdx.x) >> 5;
    if (w >= EN_TOT) return;
    long long e = w;
    int s, d;
    if (e < E_EDGES) {
        s = edge_at(ei, is64, e);
        d = edge_at(ei, is64, E_EDGES + e);
    } else {
        s = d = (int)(e - E_EDGES);
    }
    float cf4 = 0.f;
    if (lane < 4) {
        float a = g_alog[s * 8 + lane] + g_alog[d * 8 + 4 + lane];
        a = (a > 0.f) ? a : NEG_SLOPE * a;
        cf4 = __expf(a - fdec(g_max[d * 4 + lane])) / g_den[d * 4 + lane];
    }
    int h = lane >> 3;
    float cf = __shfl_sync(0xffffffffu, cf4, h);
    int c0 = h * 64 + (lane & 7) * 8;
    const float4* src4 = (const float4*)(g_out + (size_t)s * BCOLS + c0);
    float4 x0 = src4[0], x1 = src4[1];
    float* dst = g_acc + (size_t)d * HC + c0;
    asm volatile("red.global.add.v4.f32 [%0], {%1,%2,%3,%4};"
                 :: "l"(dst), "f"(cf * x0.x), "f"(cf * x0.y),
                    "f"(cf * x0.z), "f"(cf * x0.w) : "memory");
    asm volatile("red.global.add.v4.f32 [%0], {%1,%2,%3,%4};"
                 :: "l"(dst + 4), "f"(cf * x1.x), "f"(cf * x1.y),
                    "f"(cf * x1.z), "f"(cf * x1.w) : "memory");
}

// ---------------- k_final: head mean + bias + residual + relu -----------------
__global__ void k_final(const float* __restrict__ bias, float* __restrict__ out) {
    int i = blockIdx.x * blockDim.x + threadIdx.x;  // over N*16 float4 slots
    if (i >= N_NODES * 16) return;
    int n = i >> 4;
    int c = (i & 15) * 4;
    const float* acc = g_acc + (size_t)n * HC;
    float4 a0 = *(const float4*)(acc + c);
    float4 a1 = *(const float4*)(acc + 64 + c);
    float4 a2 = *(const float4*)(acc + 128 + c);
    float4 a3 = *(const float4*)(acc + 192 + c);
    float4 b  = *(const float4*)(bias + c);
    float4 r  = *(const float4*)(g_out + (size_t)n * BCOLS + 256 + c);
    float4 o;
    o.x = fmaxf(0.f, 0.25f * (a0.x + a1.x + a2.x + a3.x) + b.x + r.x);
    o.y = fmaxf(0.f, 0.25f * (a0.y + a1.y + a2.y + a3.y) + b.y + r.y);
    o.z = fmaxf(0.f, 0.25f * (a0.z + a1.z + a2.z + a3.z) + b.z + r.z);
    o.w = fmaxf(0.f, 0.25f * (a0.w + a1.w + a2.w + a3.w) + b.w + r.w);
    *(float4*)(out + (size_t)n * OUT_CH + c) = o;
}

// ---------------- launch ------------------------------------------------------
extern "C" void kernel_launch(void* const* d_in, const int* in_sizes, int n_in,
                              void* d_out, int out_size) {
    const float* x       = (const float*)d_in[0];
    const void*  ei      = d_in[1];
    const float* W       = (const float*)d_in[2];
    const float* att_src = (const float*)d_in[3];
    const float* att_dst = (const float*)d_in[4];
    const float* bias    = (const float*)d_in[5];
    const float* W_res   = (const float*)d_in[6];
    float* out = (float*)d_out;

    k_detect<<<1, 256>>>((const unsigned*)ei);
    k_pack<<<96, 256>>>(W, W_res);
    k_init<<<2048, 256>>>();
    dim3 ggrid((N_NODES + BM - 1) / BM, BCOLS / BN);
    k_gemm<<<ggrid, 256>>>(x);
    k_logits<<<256, 256>>>(att_src, att_dst);
    {
        long long total = (long long)EN_TOT * HEADS;
        int blocks = (int)((total + 255) / 256);
        k_max<<<blocks, 256>>>(ei);
        k_sum<<<blocks, 256>>>(ei);
    }
    k_scatter<<<(EN_TOT + 7) / 8, 256>>>(ei);
    k_final<<<(N_NODES * 16 + 255) / 256, 256>>>(bias, out);
}

// round 2
// speedup vs baseline: 1.2881x; 1.2881x over previous
#include <cuda_runtime.h>

#define N_NODES 50000
#define E_EDGES 800000
#define EN_TOT  (E_EDGES + N_NODES)
#define IN_CH   256
#define OUT_CH  64
#define HEADS   4
#define HC      256           // HEADS*OUT_CH
#define BCOLS   320           // 256 (W) + 64 (W_res)
#define NEG_SLOPE 0.2f

// ---------------- device scratch ---------------------------------------------
__device__ float    g_B[IN_CH * BCOLS];                 // packed [K, 320] = W | W_res
__device__ float    g_out[(size_t)N_NODES * BCOLS];     // xw (0..255) | x_res (256..319)
__device__ float    g_alog[N_NODES * 8];                // a_src[4] | a_dst[4]
__device__ float    g_den[N_NODES * HEADS];             // softmax denom -> reciprocal
__device__ float    g_acc[(size_t)N_NODES * OUT_CH];    // head-combined accumulator
__device__ int      g_is64;

// ---------------- helpers ----------------------------------------------------
__device__ __forceinline__ int edge_at(const void* ei, int is64, long long idx) {
    return is64 ? (int)((const long long*)ei)[idx] : ((const int*)ei)[idx];
}
__device__ __forceinline__ unsigned long long fma2(unsigned long long a,
                                                   unsigned long long b,
                                                   unsigned long long c) {
    unsigned long long d;
    asm("fma.rn.f32x2 %0, %1, %2, %3;" : "=l"(d) : "l"(a), "l"(b), "l"(c));
    return d;
}
__device__ __forceinline__ float2 unpk2(unsigned long long v) {
    float2 r;
    asm("mov.b64 {%0, %1}, %2;" : "=f"(r.x), "=f"(r.y) : "l"(v));
    return r;
}
__device__ __forceinline__ float lrelu(float a) {
    return (a > 0.f) ? a : NEG_SLOPE * a;
}

// ---------------- k_detect: int32 vs int64 edge_index ------------------------
__global__ void k_detect(const unsigned* __restrict__ ei_words) {
    __shared__ unsigned s_or;
    if (threadIdx.x == 0) s_or = 0;
    __syncthreads();
    unsigned v = 0;
    for (int i = threadIdx.x; i < 4096; i += blockDim.x)
        v |= ei_words[2 * i + 1];
    if (v) atomicOr(&s_or, 1u);
    __syncthreads();
    if (threadIdx.x == 0) g_is64 = (s_or == 0) ? 1 : 0;
}

// ---------------- k_pack: B = [W | W_res] ------------------------------------
__global__ void k_pack(const float* __restrict__ W, const float* __restrict__ Wr) {
    int total = IN_CH * BCOLS;
    for (int i = blockIdx.x * blockDim.x + threadIdx.x; i < total;
         i += gridDim.x * blockDim.x) {
        int k = i / BCOLS, j = i - k * BCOLS;
        g_B[i] = (j < HC) ? W[k * HC + j] : Wr[k * OUT_CH + (j - HC)];
    }
}

// ---------------- k_gemm: g_out[M,320] = X[M,256] @ g_B[256,320] --------------
// BM=256, BN=64, BK=16, 256 threads, 8x8 per thread (4 M-pairs x 8 cols).
// B tile stored pre-duplicated in smem so the inner loop has zero dup-movs:
// Bs[k][j*32 + tx*4 + half*2 + {0,1}] = dup of col (tx*8 + 2j + half).
#define BM 256
#define BN 64
#define BK 16
__global__ __launch_bounds__(256, 2) void k_gemm(const float* __restrict__ X) {
    __shared__ float As[BK][BM];        // 16 KB, [k][m]
    __shared__ float Bs[BK][2 * BN];    //  8 KB, dup'd, bank-spread layout
    int bm = blockIdx.y * BM;
    int bn = blockIdx.x * BN;
    int tid = threadIdx.x;
    int tx = tid & 7;                   // 8 cols: bn + tx*8 ..
    int ty = tid >> 3;                  // 8 rows: bm + ty*8 ..

    unsigned long long acc[4][8];
#pragma unroll
    for (int i = 0; i < 4; i++)
#pragma unroll
        for (int j = 0; j < 8; j++) acc[i][j] = 0ull;

    int arow = bm + tid;                // this thread's A row
    int bk = tid >> 4;                  // B loader: k row
    int bc0 = (tid & 15) * 4;           // B loader: 4 cols

    float4 pa[4];
    float4 pb;
    // prefetch tile 0
    {
        bool ok = arow < N_NODES;
#pragma unroll
        for (int i = 0; i < 4; i++)
            pa[i] = ok ? *(const float4*)(X + (size_t)arow * IN_CH + i * 4)
                       : make_float4(0.f, 0.f, 0.f, 0.f);
        pb = *(const float4*)(g_B + bk * BCOLS + bn + bc0);
    }

#pragma unroll 1
    for (int t = 0; t < IN_CH / BK; t++) {
        // store prefetched regs -> smem
#pragma unroll
        for (int i = 0; i < 4; i++) {
            As[i * 4 + 0][tid] = pa[i].x;
            As[i * 4 + 1][tid] = pa[i].y;
            As[i * 4 + 2][tid] = pa[i].z;
            As[i * 4 + 3][tid] = pa[i].w;
        }
        {
            float v[4] = {pb.x, pb.y, pb.z, pb.w};
#pragma unroll
            for (int u = 0; u < 4; u++) {
                int c = bc0 + u;
                int idx = ((c & 7) >> 1) * 32 + (c >> 3) * 4 + (c & 1) * 2;
                Bs[bk][idx] = v[u];
                Bs[bk][idx + 1] = v[u];
            }
        }
        __syncthreads();
        // prefetch next tile
        if (t + 1 < IN_CH / BK) {
            int k0 = (t + 1) * BK;
            bool ok = arow < N_NODES;
#pragma unroll
            for (int i = 0; i < 4; i++)
                pa[i] = ok ? *(const float4*)(X + (size_t)arow * IN_CH + k0 + i * 4)
                           : make_float4(0.f, 0.f, 0.f, 0.f);
            pb = *(const float4*)(g_B + (k0 + bk) * BCOLS + bn + bc0);
        }
        // compute
#pragma unroll
        for (int k = 0; k < BK; k++) {
            ulonglong2 a01 = *(const ulonglong2*)&As[k][ty * 8];
            ulonglong2 a23 = *(const ulonglong2*)&As[k][ty * 8 + 4];
            unsigned long long a2[4] = {a01.x, a01.y, a23.x, a23.y};
#pragma unroll
            for (int j = 0; j < 4; j++) {
                ulonglong2 b = *(const ulonglong2*)&Bs[k][j * 32 + tx * 4];
#pragma unroll
                for (int mi = 0; mi < 4; mi++) {
                    acc[mi][2 * j]     = fma2(a2[mi], b.x, acc[mi][2 * j]);
                    acc[mi][2 * j + 1] = fma2(a2[mi], b.y, acc[mi][2 * j + 1]);
                }
            }
        }
        __syncthreads();
    }

    // epilogue
#pragma unroll
    for (int mi = 0; mi < 4; mi++) {
        float va[8], vb[8];
#pragma unroll
        for (int c = 0; c < 8; c++) {
            float2 v = unpk2(acc[mi][c]);
            va[c] = v.x;
            vb[c] = v.y;
        }
        int r0 = bm + ty * 8 + 2 * mi;
        float* p0 = g_out + (size_t)r0 * BCOLS + bn + tx * 8;
        if (r0 < N_NODES) {
            *(float4*)p0 = make_float4(va[0], va[1], va[2], va[3]);
            *(float4*)(p0 + 4) = make_float4(va[4], va[5], va[6], va[7]);
        }
        if (r0 + 1 < N_NODES) {
            *(float4*)(p0 + BCOLS) = make_float4(vb[0], vb[1], vb[2], vb[3]);
            *(float4*)(p0 + BCOLS + 4) = make_float4(vb[4], vb[5], vb[6], vb[7]);
        }
    }
}

// ---------------- k_logits: per-node attention logits -------------------------
__global__ void k_logits(const float* __restrict__ att_src,
                         const float* __restrict__ att_dst) {
    __shared__ float satt[512];
    for (int i = threadIdx.x; i < 256; i += blockDim.x) {
        satt[i]       = att_src[i];
        satt[256 + i] = att_dst[i];
    }
    __syncthreads();
    int lane = threadIdx.x & 31;
    int wid = (blockIdx.x * blockDim.x + threadIdx.x) >> 5;
    int nwarps = (gridDim.x * blockDim.x) >> 5;
    for (int n = wid; n < N_NODES; n += nwarps) {
        const float* row = g_out + (size_t)n * BCOLS;
#pragma unroll
        for (int h = 0; h < HEADS; h++) {
            float v0 = row[h * 64 + lane];
            float v1 = row[h * 64 + 32 + lane];
            float ps = v0 * satt[h * 64 + lane] + v1 * satt[h * 64 + 32 + lane];
            float pd = v0 * satt[256 + h * 64 + lane] + v1 * satt[256 + h * 64 + 32 + lane];
#pragma unroll
            for (int o = 16; o; o >>= 1) {
                ps += __shfl_xor_sync(0xffffffffu, ps, o);
                pd += __shfl_xor_sync(0xffffffffu, pd, o);
            }
            if (lane == 0) {
                g_alog[n * 8 + h]     = ps;
                g_alog[n * 8 + 4 + h] = pd;
            }
        }
    }
}

// ---------------- k_init: zero accumulators ----------------------------------
__global__ void k_init() {
    long long idx = blockIdx.x * (long long)blockDim.x + threadIdx.x;
    long long stride = (long long)gridDim.x * blockDim.x;
    long long nacc4 = (long long)N_NODES * OUT_CH / 4;
    float4 z = make_float4(0.f, 0.f, 0.f, 0.f);
    for (long long i = idx; i < nacc4; i += stride) ((float4*)g_acc)[i] = z;
    for (long long i = idx; i < (long long)N_NODES * HEADS; i += stride)
        g_den[i] = 0.f;
}

// ---------------- k_sum: segment sum of exp(alpha), no max-sub ----------------
__global__ void k_sum(const void* __restrict__ ei) {
    int is64 = g_is64;
    int i = blockIdx.x * blockDim.x + threadIdx.x;
    if (i >= EN_TOT * HEADS) return;
    int e = i >> 2;
    int h = i & 3;
    int s, d;
    if (e < E_EDGES) {
        s = edge_at(ei, is64, e);
        d = edge_at(ei, is64, E_EDGES + e);
    } else {
        s = d = e - E_EDGES;
    }
    float a = lrelu(g_alog[s * 8 + h] + g_alog[d * 8 + 4 + h]);
    atomicAdd(&g_den[d * 4 + h], __expf(a));
}

// ---------------- k_invden: reciprocal of denominators ------------------------
__global__ void k_invden() {
    int i = blockIdx.x * blockDim.x + threadIdx.x;
    if (i < N_NODES * HEADS) g_den[i] = 1.0f / g_den[i];
}

// ---------------- k_scatter: warp/edge, head-combined 64-float message --------
__global__ void k_scatter(const void* __restrict__ ei) {
    int is64 = g_is64;
    int lane = threadIdx.x & 31;
    long long w = ((long long)blockIdx.x * blockDim.x + threadIdx.x) >> 5;
    if (w >= EN_TOT) return;
    int s, d;
    if (w < E_EDGES) {
        s = edge_at(ei, is64, w);
        d = edge_at(ei, is64, E_EDGES + w);
    } else {
        s = d = (int)(w - E_EDGES);
    }
    float wt = 0.f;
    if (lane < 4) {
        float a = lrelu(g_alog[s * 8 + lane] + g_alog[d * 8 + 4 + lane]);
        wt = __expf(a) * g_den[d * 4 + lane];
    }
    float w0 = __shfl_sync(0xffffffffu, wt, 0);
    float w1 = __shfl_sync(0xffffffffu, wt, 1);
    float w2 = __shfl_sync(0xffffffffu, wt, 2);
    float w3 = __shfl_sync(0xffffffffu, wt, 3);

    const float* src = g_out + (size_t)s * BCOLS + lane * 2;
    float2 x0 = *(const float2*)(src);
    float2 x1 = *(const float2*)(src + 64);
    float2 x2 = *(const float2*)(src + 128);
    float2 x3 = *(const float2*)(src + 192);
    float mx = fmaf(w0, x0.x, fmaf(w1, x1.x, fmaf(w2, x2.x, w3 * x3.x)));
    float my = fmaf(w0, x0.y, fmaf(w1, x1.y, fmaf(w2, x2.y, w3 * x3.y)));

    float* dst = g_acc + (size_t)d * OUT_CH + lane * 2;
    asm volatile("red.global.add.v2.f32 [%0], {%1,%2};"
                 :: "l"(dst), "f"(mx), "f"(my) : "memory");
}

// ---------------- k_final: head mean + bias + residual + relu -----------------
__global__ void k_final(const float* __restrict__ bias, float* __restrict__ out) {
    int i = blockIdx.x * blockDim.x + threadIdx.x;  // over N*16 float4 slots
    if (i >= N_NODES * 16) return;
    int n = i >> 4;
    int c = (i & 15) * 4;
    float4 a = *(const float4*)(g_acc + (size_t)n * OUT_CH + c);
    float4 b = *(const float4*)(bias + c);
    float4 r = *(const float4*)(g_out + (size_t)n * BCOLS + 256 + c);
    float4 o;
    o.x = fmaxf(0.f, 0.25f * a.x + b.x + r.x);
    o.y = fmaxf(0.f, 0.25f * a.y + b.y + r.y);
    o.z = fmaxf(0.f, 0.25f * a.z + b.z + r.z);
    o.w = fmaxf(0.f, 0.25f * a.w + b.w + r.w);
    *(float4*)(out + (size_t)n * OUT_CH + c) = o;
}

// ---------------- launch ------------------------------------------------------
extern "C" void kernel_launch(void* const* d_in, const int* in_sizes, int n_in,
                              void* d_out, int out_size) {
    const float* x       = (const float*)d_in[0];
    const void*  ei      = d_in[1];
    const float* W       = (const float*)d_in[2];
    const float* att_src = (const float*)d_in[3];
    const float* att_dst = (const float*)d_in[4];
    const float* bias    = (const float*)d_in[5];
    const float* W_res   = (const float*)d_in[6];
    float* out = (float*)d_out;

    k_detect<<<1, 256>>>((const unsigned*)ei);
    k_pack<<<96, 256>>>(W, W_res);
    k_init<<<1024, 256>>>();
    dim3 ggrid(BCOLS / BN, (N_NODES + BM - 1) / BM);   // N fastest: A-tile L2 reuse
    k_gemm<<<ggrid, 256>>>(x);
    k_logits<<<256, 256>>>(att_src, att_dst);
    k_sum<<<(EN_TOT * HEADS + 255) / 256, 256>>>(ei);
    k_invden<<<(N_NODES * HEADS + 255) / 256, 256>>>();
    k_scatter<<<(int)(((long long)EN_TOT * 32 + 255) / 256), 256>>>(ei);
    k_final<<<(N_NODES * 16 + 255) / 256, 256>>>(bias, out);
}

// round 4
// speedup vs baseline: 2.0399x; 1.5837x over previous
#include <cuda_runtime.h>
#include <cuda_bf16.h>
#include <cstdint>

#define N_NODES 50000
#define E_EDGES 800000
#define EN_TOT  (E_EDGES + N_NODES)
#define IN_CH   256
#define OUT_CH  64
#define HEADS   4
#define HC      256
#define BCOLS   320           // 256 (W) + 64 (W_res)
#define NEG_SLOPE 0.2f

// ---------------- device scratch ---------------------------------------------
__device__ float    g_Bt[BCOLS * IN_CH];                // B^T: [320][256], k contiguous
__device__ float    g_out[(size_t)N_NODES * BCOLS];     // xw (0..255) | x_res (256..319)
__device__ float    g_alog[N_NODES * 8];                // a_src[4] | a_dst[4]
__device__ float    g_den[N_NODES * HEADS];
__device__ float    g_acc[(size_t)N_NODES * OUT_CH];
__device__ int      g_is64;

// ---------------- helpers ----------------------------------------------------
__device__ __forceinline__ int edge_at(const void* ei, int is64, long long idx) {
    return is64 ? (int)((const long long*)ei)[idx] : ((const int*)ei)[idx];
}
__device__ __forceinline__ float lrelu(float a) {
    return (a > 0.f) ? a : NEG_SLOPE * a;
}
// split a float pair into packed bf16x2 hi and lo parts
__device__ __forceinline__ void cvt_hl(float x, float y, uint32_t& h, uint32_t& l) {
    __nv_bfloat162 hb = __floats2bfloat162_rn(x, y);   // x -> lo half, y -> hi half
    float2 hf = __bfloat1622float2(hb);
    __nv_bfloat162 lb = __floats2bfloat162_rn(x - hf.x, y - hf.y);
    h = *(uint32_t*)&hb;
    l = *(uint32_t*)&lb;
}
#define MMA_BF16(d, a, b)                                                     \
    asm volatile(                                                             \
        "mma.sync.aligned.m16n8k16.row.col.f32.bf16.bf16.f32 "                \
        "{%0,%1,%2,%3}, {%4,%5,%6,%7}, {%8,%9}, {%0,%1,%2,%3};"               \
        : "+f"(d[0]), "+f"(d[1]), "+f"(d[2]), "+f"(d[3])                      \
        : "r"(a.x), "r"(a.y), "r"(a.z), "r"(a.w), "r"(b.x), "r"(b.y))

// ---------------- k_detect ----------------------------------------------------
__global__ void k_detect(const unsigned* __restrict__ ei_words) {
    __shared__ unsigned s_or;
    if (threadIdx.x == 0) s_or = 0;
    __syncthreads();
    unsigned v = 0;
    for (int i = threadIdx.x; i < 4096; i += blockDim.x)
        v |= ei_words[2 * i + 1];
    if (v) atomicOr(&s_or, 1u);
    __syncthreads();
    if (threadIdx.x == 0) g_is64 = (s_or == 0) ? 1 : 0;
}

// ---------------- k_pack: g_Bt[j][k] = [W | W_res]^T --------------------------
__global__ void k_pack(const float* __restrict__ W, const float* __restrict__ Wr) {
    int total = BCOLS * IN_CH;
    for (int i = blockIdx.x * blockDim.x + threadIdx.x; i < total;
         i += gridDim.x * blockDim.x) {
        int j = i / IN_CH, k = i - j * IN_CH;
        g_Bt[i] = (j < HC) ? W[k * HC + j] : Wr[k * OUT_CH + (j - HC)];
    }
}

// ---------------- k_gemm: mma.sync bf16 3-term split --------------------------
// BM=128, BN=64, BK=32 chunk. 8 warps in 4x2; warp tile 32x32.
// smem in fragment order: A_s[hl][kstep][mtile][lane][reg], B_s[hl][kstep][ntile][lane][reg]
__global__ __launch_bounds__(256, 2) void k_gemm(const float* __restrict__ X) {
    __shared__ uint32_t A_s[2][2][8][32][4];   // 16 KB
    __shared__ uint32_t B_s[2][2][8][32][2];   //  8 KB
    int tid = threadIdx.x;
    int lane = tid & 31;
    int wid = tid >> 5;
    int bm = blockIdx.y * 128;
    int bn = blockIdx.x * 64;
    int mrow = wid >> 1;          // 0..3 -> mtiles {2*mrow, 2*mrow+1}
    int ncol = wid & 1;           // 0..1 -> ntiles {4*ncol .. 4*ncol+3}

    float acc[2][4][4];
#pragma unroll
    for (int i = 0; i < 2; i++)
#pragma unroll
        for (int j = 0; j < 4; j++)
#pragma unroll
            for (int q = 0; q < 4; q++) acc[i][j][q] = 0.f;

    float4 pa[4], pb[2];
    // prefetch chunk 0
    {
#pragma unroll
        for (int i = 0; i < 4; i++) {
            int v = tid + 256 * i;
            int r = v >> 3, c0 = (v & 7) * 4;
            int gr = bm + r;
            pa[i] = (gr < N_NODES)
                        ? *(const float4*)(X + (size_t)gr * IN_CH + c0)
                        : make_float4(0.f, 0.f, 0.f, 0.f);
        }
#pragma unroll
        for (int i = 0; i < 2; i++) {
            int v = tid + 256 * i;
            int n = v >> 3, c0 = (v & 7) * 4;
            pb[i] = *(const float4*)(g_Bt + (bn + n) * IN_CH + c0);
        }
    }

#pragma unroll 1
    for (int t = 0; t < IN_CH / 32; t++) {
        // ---- convert + store to fragment-ordered smem ----
#pragma unroll
        for (int i = 0; i < 4; i++) {
            int v = tid + 256 * i;
            int r = v >> 3, c0 = (v & 7) * 4;
            int p0 = c0 >> 1;                         // even pair index in [0,16)
            uint32_t h0, l0, h1, l1;
            cvt_hl(pa[i].x, pa[i].y, h0, l0);
            cvt_hl(pa[i].z, pa[i].w, h1, l1);
            int ks = p0 >> 3;
            int reg = ((r >> 3) & 1) | (((p0 >> 2) & 1) << 1);
            int ln = (r & 7) * 4 + (p0 & 3);
            int mt = r >> 4;
            A_s[0][ks][mt][ln][reg] = h0;
            A_s[1][ks][mt][ln][reg] = l0;
            A_s[0][ks][mt][ln + 1][reg] = h1;
            A_s[1][ks][mt][ln + 1][reg] = l1;
        }
#pragma unroll
        for (int i = 0; i < 2; i++) {
            int v = tid + 256 * i;
            int n = v >> 3, c0 = (v & 7) * 4;
            int p0 = c0 >> 1;
            uint32_t h0, l0, h1, l1;
            cvt_hl(pb[i].x, pb[i].y, h0, l0);
            cvt_hl(pb[i].z, pb[i].w, h1, l1);
            int ks = p0 >> 3;
            int reg = (p0 >> 2) & 1;
            int ln = (n & 7) * 4 + (p0 & 3);
            int nt = n >> 3;
            B_s[0][ks][nt][ln][reg] = h0;
            B_s[1][ks][nt][ln][reg] = l0;
            B_s[0][ks][nt][ln + 1][reg] = h1;
            B_s[1][ks][nt][ln + 1][reg] = l1;
        }
        __syncthreads();
        // ---- prefetch next chunk (overlaps MMA) ----
        if (t + 1 < IN_CH / 32) {
            int k0 = (t + 1) * 32;
#pragma unroll
            for (int i = 0; i < 4; i++) {
                int v = tid + 256 * i;
                int r = v >> 3, c0 = (v & 7) * 4;
                int gr = bm + r;
                pa[i] = (gr < N_NODES)
                            ? *(const float4*)(X + (size_t)gr * IN_CH + k0 + c0)
                            : make_float4(0.f, 0.f, 0.f, 0.f);
            }
#pragma unroll
            for (int i = 0; i < 2; i++) {
                int v = tid + 256 * i;
                int n = v >> 3, c0 = (v & 7) * 4;
                pb[i] = *(const float4*)(g_Bt + (bn + n) * IN_CH + k0 + c0);
            }
        }
        // ---- compute: 2 ksteps x 3 terms x 2x4 tiles ----
#pragma unroll
        for (int ks = 0; ks < 2; ks++) {
            uint4 ah[2], al[2];
            uint2 bh[4], bl[4];
#pragma unroll
            for (int mt = 0; mt < 2; mt++) {
                ah[mt] = *(const uint4*)&A_s[0][ks][mrow * 2 + mt][lane][0];
                al[mt] = *(const uint4*)&A_s[1][ks][mrow * 2 + mt][lane][0];
            }
#pragma unroll
            for (int nt = 0; nt < 4; nt++) {
                bh[nt] = *(const uint2*)&B_s[0][ks][ncol * 4 + nt][lane][0];
                bl[nt] = *(const uint2*)&B_s[1][ks][ncol * 4 + nt][lane][0];
            }
#pragma unroll
            for (int mt = 0; mt < 2; mt++)
#pragma unroll
                for (int nt = 0; nt < 4; nt++) {
                    MMA_BF16(acc[mt][nt], ah[mt], bh[nt]);
                    MMA_BF16(acc[mt][nt], ah[mt], bl[nt]);
                    MMA_BF16(acc[mt][nt], al[mt], bh[nt]);
                }
        }
        __syncthreads();
    }

    // ---- epilogue: write fp32 frags to g_out ----
#pragma unroll
    for (int mt = 0; mt < 2; mt++) {
#pragma unroll
        for (int nt = 0; nt < 4; nt++) {
            int row0 = bm + (mrow * 2 + mt) * 16 + (lane >> 2);
            int col = bn + (ncol * 4 + nt) * 8 + (lane & 3) * 2;
            float* p = g_out + (size_t)row0 * BCOLS + col;
            if (row0 < N_NODES)
                *(float2*)p = make_float2(acc[mt][nt][0], acc[mt][nt][1]);
            if (row0 + 8 < N_NODES)
                *(float2*)(p + 8 * BCOLS) = make_float2(acc[mt][nt][2], acc[mt][nt][3]);
        }
    }
}

// ---------------- k_logits ----------------------------------------------------
__global__ void k_logits(const float* __restrict__ att_src,
                         const float* __restrict__ att_dst) {
    __shared__ float satt[512];
    for (int i = threadIdx.x; i < 256; i += blockDim.x) {
        satt[i]       = att_src[i];
        satt[256 + i] = att_dst[i];
    }
    __syncthreads();
    int lane = threadIdx.x & 31;
    int wid = (blockIdx.x * blockDim.x + threadIdx.x) >> 5;
    int nwarps = (gridDim.x * blockDim.x) >> 5;
    for (int n = wid; n < N_NODES; n += nwarps) {
        const float* row = g_out + (size_t)n * BCOLS;
#pragma unroll
        for (int h = 0; h < HEADS; h++) {
            float v0 = row[h * 64 + lane];
            float v1 = row[h * 64 + 32 + lane];
            float ps = v0 * satt[h * 64 + lane] + v1 * satt[h * 64 + 32 + lane];
            float pd = v0 * satt[256 + h * 64 + lane] + v1 * satt[256 + h * 64 + 32 + lane];
#pragma unroll
            for (int o = 16; o; o >>= 1) {
                ps += __shfl_xor_sync(0xffffffffu, ps, o);
                pd += __shfl_xor_sync(0xffffffffu, pd, o);
            }
            if (lane == 0) {
                g_alog[n * 8 + h]     = ps;
                g_alog[n * 8 + 4 + h] = pd;
            }
        }
    }
}

// ---------------- k_init ------------------------------------------------------
__global__ void k_init() {
    long long idx = blockIdx.x * (long long)blockDim.x + threadIdx.x;
    long long stride = (long long)gridDim.x * blockDim.x;
    long long nacc4 = (long long)N_NODES * OUT_CH / 4;
    float4 z = make_float4(0.f, 0.f, 0.f, 0.f);
    for (long long i = idx; i < nacc4; i += stride) ((float4*)g_acc)[i] = z;
    for (long long i = idx; i < (long long)N_NODES * HEADS; i += stride)
        g_den[i] = 0.f;
}

// ---------------- k_sum -------------------------------------------------------
__global__ void k_sum(const void* __restrict__ ei) {
    int is64 = g_is64;
    int i = blockIdx.x * blockDim.x + threadIdx.x;
    if (i >= EN_TOT * HEADS) return;
    int e = i >> 2;
    int h = i & 3;
    int s, d;
    if (e < E_EDGES) {
        s = edge_at(ei, is64, e);
        d = edge_at(ei, is64, E_EDGES + e);
    } else {
        s = d = e - E_EDGES;
    }
    float a = lrelu(g_alog[s * 8 + h] + g_alog[d * 8 + 4 + h]);
    atomicAdd(&g_den[d * 4 + h], __expf(a));
}

// ---------------- k_invden ----------------------------------------------------
__global__ void k_invden() {
    int i = blockIdx.x * blockDim.x + threadIdx.x;
    if (i < N_NODES * HEADS) g_den[i] = 1.0f / g_den[i];
}

// ---------------- k_scatter ---------------------------------------------------
__global__ void k_scatter(const void* __restrict__ ei) {
    int is64 = g_is64;
    int lane = threadIdx.x & 31;
    long long w = ((long long)blockIdx.x * blockDim.x + threadIdx.x) >> 5;
    if (w >= EN_TOT) return;
    int s, d;
    if (w < E_EDGES) {
        s = edge_at(ei, is64, w);
        d = edge_at(ei, is64, E_EDGES + w);
    } else {
        s = d = (int)(w - E_EDGES);
    }
    float wt = 0.f;
    if (lane < 4) {
        float a = lrelu(g_alog[s * 8 + lane] + g_alog[d * 8 + 4 + lane]);
        wt = __expf(a) * g_den[d * 4 + lane];
    }
    float w0 = __shfl_sync(0xffffffffu, wt, 0);
    float w1 = __shfl_sync(0xffffffffu, wt, 1);
    float w2 = __shfl_sync(0xffffffffu, wt, 2);
    float w3 = __shfl_sync(0xffffffffu, wt, 3);

    const float* src = g_out + (size_t)s * BCOLS + lane * 2;
    float2 x0 = *(const float2*)(src);
    float2 x1 = *(const float2*)(src + 64);
    float2 x2 = *(const float2*)(src + 128);
    float2 x3 = *(const float2*)(src + 192);
    float mx = fmaf(w0, x0.x, fmaf(w1, x1.x, fmaf(w2, x2.x, w3 * x3.x)));
    float my = fmaf(w0, x0.y, fmaf(w1, x1.y, fmaf(w2, x2.y, w3 * x3.y)));

    float* dst = g_acc + (size_t)d * OUT_CH + lane * 2;
    asm volatile("red.global.add.v2.f32 [%0], {%1,%2};"
                 :: "l"(dst), "f"(mx), "f"(my) : "memory");
}

// ---------------- k_final -----------------------------------------------------
__global__ void k_final(const float* __restrict__ bias, float* __restrict__ out) {
    int i = blockIdx.x * blockDim.x + threadIdx.x;
    if (i >= N_NODES * 16) return;
    int n = i >> 4;
    int c = (i & 15) * 4;
    float4 a = *(const float4*)(g_acc + (size_t)n * OUT_CH + c);
    float4 b = *(const float4*)(bias + c);
    float4 r = *(const float4*)(g_out + (size_t)n * BCOLS + 256 + c);
    float4 o;
    o.x = fmaxf(0.f, 0.25f * a.x + b.x + r.x);
    o.y = fmaxf(0.f, 0.25f * a.y + b.y + r.y);
    o.z = fmaxf(0.f, 0.25f * a.z + b.z + r.z);
    o.w = fmaxf(0.f, 0.25f * a.w + b.w + r.w);
    *(float4*)(out + (size_t)n * OUT_CH + c) = o;
}

// ---------------- launch ------------------------------------------------------
extern "C" void kernel_launch(void* const* d_in, const int* in_sizes, int n_in,
                              void* d_out, int out_size) {
    const float* x       = (const float*)d_in[0];
    const void*  ei      = d_in[1];
    const float* W       = (const float*)d_in[2];
    const float* att_src = (const float*)d_in[3];
    const float* att_dst = (const float*)d_in[4];
    const float* bias    = (const float*)d_in[5];
    const float* W_res   = (const float*)d_in[6];
    float* out = (float*)d_out;

    k_detect<<<1, 256>>>((const unsigned*)ei);
    k_pack<<<96, 256>>>(W, W_res);
    k_init<<<1024, 256>>>();
    dim3 ggrid(BCOLS / 64, (N_NODES + 127) / 128);
    k_gemm<<<ggrid, 256>>>(x);
    k_logits<<<256, 256>>>(att_src, att_dst);
    k_sum<<<(EN_TOT * HEADS + 255) / 256, 256>>>(ei);
    k_invden<<<(N_NODES * HEADS + 255) / 256, 256>>>();
    k_scatter<<<(int)(((long long)EN_TOT * 32 + 255) / 256), 256>>>(ei);
    k_final<<<(N_NODES * 16 + 255) / 256, 256>>>(bias, out);
}

// round 5
// speedup vs baseline: 2.3120x; 1.1334x over previous
#include <cuda_runtime.h>
#include <cuda_bf16.h>
#include <cstdint>

#define N_NODES 50000
#define E_EDGES 800000
#define EN_TOT  (E_EDGES + N_NODES)
#define IN_CH   256
#define OUT_CH  64
#define HEADS   4
#define HC      256
#define BCOLS   320
#define NEG_SLOPE 0.2f
#define MBLK    391            // ceil(50000/128)

// ---------------- device scratch ---------------------------------------------
// A fragments: [mb][kc8][hl2][ks2][mt8][lane32] uint4
__device__ uint4    g_Af[MBLK * 8192];
// B fragments: [nb5][kc8][ks2][nt8][lane32] uint4 = {bh0,bh1,bl0,bl1}
__device__ uint4    g_Bf[5 * 4096];
__device__ float    g_out[(size_t)N_NODES * BCOLS];     // xw | x_res
__device__ float    g_alog[N_NODES * 8];                // a_src[4] | a_dst[4]
__device__ float    g_den[N_NODES * HEADS];
__device__ float    g_acc[(size_t)N_NODES * OUT_CH];
__device__ int      g_is64;

// ---------------- helpers ----------------------------------------------------
__device__ __forceinline__ int edge_at(const void* ei, int is64, long long idx) {
    return is64 ? (int)((const long long*)ei)[idx] : ((const int*)ei)[idx];
}
__device__ __forceinline__ float lrelu(float a) {
    return (a > 0.f) ? a : NEG_SLOPE * a;
}
__device__ __forceinline__ void cvt_hl(float x, float y, uint32_t& h, uint32_t& l) {
    __nv_bfloat162 hb = __floats2bfloat162_rn(x, y);   // x -> low half
    float2 hf = __bfloat1622float2(hb);
    __nv_bfloat162 lb = __floats2bfloat162_rn(x - hf.x, y - hf.y);
    h = *(uint32_t*)&hb;
    l = *(uint32_t*)&lb;
}
#define MMA_BF16(d, a, b0, b1)                                                \
    asm volatile(                                                             \
        "mma.sync.aligned.m16n8k16.row.col.f32.bf16.bf16.f32 "                \
        "{%0,%1,%2,%3}, {%4,%5,%6,%7}, {%8,%9}, {%0,%1,%2,%3};"               \
        : "+f"(d[0]), "+f"(d[1]), "+f"(d[2]), "+f"(d[3])                      \
        : "r"(a.x), "r"(a.y), "r"(a.z), "r"(a.w), "r"(b0), "r"(b1))

// ---------------- k_detect ----------------------------------------------------
__global__ void k_detect(const unsigned* __restrict__ ei_words) {
    __shared__ unsigned s_or;
    if (threadIdx.x == 0) s_or = 0;
    __syncthreads();
    unsigned v = 0;
    for (int i = threadIdx.x; i < 4096; i += blockDim.x)
        v |= ei_words[2 * i + 1];
    if (v) atomicOr(&s_or, 1u);
    __syncthreads();
    if (threadIdx.x == 0) g_is64 = (s_or == 0) ? 1 : 0;
}

// ---------------- k_prep: X -> bf16 hi/lo fragments in global ----------------
// thread = (mb, kc, ks, mt, lane); 4096 threads per mblock
__global__ void k_prep(const float* __restrict__ X) {
    int t = blockIdx.x * blockDim.x + threadIdx.x;
    if (t >= MBLK * 4096) return;
    int lane = t & 31;
    int mt = (t >> 5) & 7;
    int ks = (t >> 8) & 1;
    int kc = (t >> 9) & 7;
    int mb = t >> 12;

    int r0 = mb * 128 + mt * 16 + (lane >> 2);       // rows r0, r0+8
    int tt = lane & 3;
    int k0 = kc * 32 + (ks * 8 + tt) * 2;            // k pairs: k0, k0+8 (and +1)

    float2 v[4];
    v[0] = (r0 < N_NODES) ? *(const float2*)(X + (size_t)r0 * IN_CH + k0)
                          : make_float2(0.f, 0.f);
    v[1] = (r0 + 8 < N_NODES) ? *(const float2*)(X + (size_t)(r0 + 8) * IN_CH + k0)
                              : make_float2(0.f, 0.f);
    v[2] = (r0 < N_NODES) ? *(const float2*)(X + (size_t)r0 * IN_CH + k0 + 8)
                          : make_float2(0.f, 0.f);
    v[3] = (r0 + 8 < N_NODES) ? *(const float2*)(X + (size_t)(r0 + 8) * IN_CH + k0 + 8)
                              : make_float2(0.f, 0.f);
    uint4 hv, lv;
    cvt_hl(v[0].x, v[0].y, hv.x, lv.x);
    cvt_hl(v[1].x, v[1].y, hv.y, lv.y);
    cvt_hl(v[2].x, v[2].y, hv.z, lv.z);
    cvt_hl(v[3].x, v[3].y, hv.w, lv.w);

    int base = mb * 8192 + kc * 1024 + ks * 256 + mt * 32 + lane;
    g_Af[base] = hv;              // hl=0
    g_Af[base + 512] = lv;        // hl=1
}

// ---------------- k_packB: W|W_res -> B fragments -----------------------------
__global__ void k_packB(const float* __restrict__ W, const float* __restrict__ Wr) {
    int t = blockIdx.x * blockDim.x + threadIdx.x;
    if (t >= 5 * 4096) return;
    int lane = t & 31;
    int nt = (t >> 5) & 7;
    int ks = (t >> 8) & 1;
    int kc = (t >> 9) & 7;
    int nb = t >> 12;

    int col = nb * 64 + nt * 8 + (lane >> 2);
    int tt = lane & 3;
    int k0 = kc * 32 + ks * 16 + tt * 2;

    float b00, b01, b10, b11;
    if (col < HC) {
        b00 = W[(k0) * HC + col];     b01 = W[(k0 + 1) * HC + col];
        b10 = W[(k0 + 8) * HC + col]; b11 = W[(k0 + 9) * HC + col];
    } else {
        int c = col - HC;
        b00 = Wr[(k0) * OUT_CH + c];     b01 = Wr[(k0 + 1) * OUT_CH + c];
        b10 = Wr[(k0 + 8) * OUT_CH + c]; b11 = Wr[(k0 + 9) * OUT_CH + c];
    }
    uint4 o;
    cvt_hl(b00, b01, o.x, o.z);
    cvt_hl(b10, b11, o.y, o.w);
    g_Bf[nb * 4096 + kc * 512 + ks * 256 + nt * 32 + lane] = o;
}

// ---------------- k_gemm: no-smem mma.sync from global fragments --------------
__global__ __launch_bounds__(256) void k_gemm() {
    int tid = threadIdx.x;
    int lane = tid & 31;
    int wid = tid >> 5;
    int mrow = wid >> 1;          // 0..3
    int ncol = wid & 1;           // 0..1
    int mb = blockIdx.y;
    int nb = blockIdx.x;

    float acc[2][4][4];
#pragma unroll
    for (int i = 0; i < 2; i++)
#pragma unroll
        for (int j = 0; j < 4; j++)
#pragma unroll
            for (int q = 0; q < 4; q++) acc[i][j][q] = 0.f;

    const uint4* Ab = g_Af + mb * 8192;
    const uint4* Bb = g_Bf + nb * 4096;

#pragma unroll 1
    for (int kc = 0; kc < 8; kc++) {
        const uint4* Ak = Ab + kc * 1024;
        const uint4* Bk = Bb + kc * 512;
        uint4 ah[2][2], al[2][2];
#pragma unroll
        for (int ks = 0; ks < 2; ks++)
#pragma unroll
            for (int mt = 0; mt < 2; mt++) {
                int m = mrow * 2 + mt;
                ah[ks][mt] = Ak[ks * 256 + m * 32 + lane];
                al[ks][mt] = Ak[512 + ks * 256 + m * 32 + lane];
            }
#pragma unroll
        for (int ks = 0; ks < 2; ks++)
#pragma unroll
            for (int j = 0; j < 4; j++) {
                uint4 bv = Bk[ks * 256 + (ncol * 4 + j) * 32 + lane];
#pragma unroll
                for (int mt = 0; mt < 2; mt++) {
                    MMA_BF16(acc[mt][j], ah[ks][mt], bv.x, bv.y);
                    MMA_BF16(acc[mt][j], ah[ks][mt], bv.z, bv.w);
                    MMA_BF16(acc[mt][j], al[ks][mt], bv.x, bv.y);
                }
            }
    }

#pragma unroll
    for (int mt = 0; mt < 2; mt++)
#pragma unroll
        for (int nt = 0; nt < 4; nt++) {
            int row0 = mb * 128 + (mrow * 2 + mt) * 16 + (lane >> 2);
            int col = nb * 64 + (ncol * 4 + nt) * 8 + (lane & 3) * 2;
            float* p = g_out + (size_t)row0 * BCOLS + col;
            if (row0 < N_NODES)
                *(float2*)p = make_float2(acc[mt][nt][0], acc[mt][nt][1]);
            if (row0 + 8 < N_NODES)
                *(float2*)(p + 8 * BCOLS) = make_float2(acc[mt][nt][2], acc[mt][nt][3]);
        }
}

// ---------------- k_logits ----------------------------------------------------
__global__ void k_logits(const float* __restrict__ att_src,
                         const float* __restrict__ att_dst) {
    __shared__ float satt[512];
    for (int i = threadIdx.x; i < 256; i += blockDim.x) {
        satt[i]       = att_src[i];
        satt[256 + i] = att_dst[i];
    }
    __syncthreads();
    int lane = threadIdx.x & 31;
    int wid = (blockIdx.x * blockDim.x + threadIdx.x) >> 5;
    int nwarps = (gridDim.x * blockDim.x) >> 5;
    for (int n = wid; n < N_NODES; n += nwarps) {
        const float* row = g_out + (size_t)n * BCOLS;
#pragma unroll
        for (int h = 0; h < HEADS; h++) {
            float v0 = row[h * 64 + lane];
            float v1 = row[h * 64 + 32 + lane];
            float ps = v0 * satt[h * 64 + lane] + v1 * satt[h * 64 + 32 + lane];
            float pd = v0 * satt[256 + h * 64 + lane] + v1 * satt[256 + h * 64 + 32 + lane];
#pragma unroll
            for (int o = 16; o; o >>= 1) {
                ps += __shfl_xor_sync(0xffffffffu, ps, o);
                pd += __shfl_xor_sync(0xffffffffu, pd, o);
            }
            if (lane == 0) {
                g_alog[n * 8 + h]     = ps;
                g_alog[n * 8 + 4 + h] = pd;
            }
        }
    }
}

// ---------------- k_init ------------------------------------------------------
__global__ void k_init() {
    long long idx = blockIdx.x * (long long)blockDim.x + threadIdx.x;
    long long stride = (long long)gridDim.x * blockDim.x;
    long long nacc4 = (long long)N_NODES * OUT_CH / 4;
    float4 z = make_float4(0.f, 0.f, 0.f, 0.f);
    for (long long i = idx; i < nacc4; i += stride) ((float4*)g_acc)[i] = z;
    for (long long i = idx; i < (long long)N_NODES * HEADS; i += stride)
        g_den[i] = 0.f;
}

// ---------------- k_sum: 1 thread = 1 edge, 4 heads, red.v4 -------------------
__global__ void k_sum(const void* __restrict__ ei) {
    int is64 = g_is64;
    int e = blockIdx.x * blockDim.x + threadIdx.x;
    if (e >= EN_TOT) return;
    int s, d;
    if (e < E_EDGES) {
        s = edge_at(ei, is64, e);
        d = edge_at(ei, is64, E_EDGES + e);
    } else {
        s = d = e - E_EDGES;
    }
    float4 as = *(const float4*)(g_alog + s * 8);
    float4 ad = *(const float4*)(g_alog + d * 8 + 4);
    float e0 = __expf(lrelu(as.x + ad.x));
    float e1 = __expf(lrelu(as.y + ad.y));
    float e2 = __expf(lrelu(as.z + ad.z));
    float e3 = __expf(lrelu(as.w + ad.w));
    float* dst = g_den + d * 4;
    asm volatile("red.global.add.v4.f32 [%0], {%1,%2,%3,%4};"
                 :: "l"(dst), "f"(e0), "f"(e1), "f"(e2), "f"(e3) : "memory");
}

// ---------------- k_invden ----------------------------------------------------
__global__ void k_invden() {
    int i = blockIdx.x * blockDim.x + threadIdx.x;
    if (i < N_NODES * HEADS) g_den[i] = 1.0f / g_den[i];
}

// ---------------- k_scatter: 16 lanes/edge, red.v4 ----------------------------
__global__ void k_scatter(const void* __restrict__ ei) {
    int is64 = g_is64;
    int lane = threadIdx.x & 31;
    long long e = ((long long)blockIdx.x * blockDim.x + threadIdx.x) >> 4;
    if (e >= EN_TOT) return;
    int sub = lane & 15;
    int s, d;
    if (e < E_EDGES) {
        s = edge_at(ei, is64, e);
        d = edge_at(ei, is64, E_EDGES + e);
    } else {
        s = d = (int)(e - E_EDGES);
    }
    float wt = 0.f;
    if (sub < 4) {
        float a = lrelu(g_alog[s * 8 + sub] + g_alog[d * 8 + 4 + sub]);
        wt = __expf(a) * g_den[d * 4 + sub];
    }
    int base = lane & 16;
    float w0 = __shfl_sync(0xffffffffu, wt, base + 0);
    float w1 = __shfl_sync(0xffffffffu, wt, base + 1);
    float w2 = __shfl_sync(0xffffffffu, wt, base + 2);
    float w3 = __shfl_sync(0xffffffffu, wt, base + 3);

    int c0 = sub * 4;
    const float* src = g_out + (size_t)s * BCOLS + c0;
    float4 x0 = *(const float4*)(src);
    float4 x1 = *(const float4*)(src + 64);
    float4 x2 = *(const float4*)(src + 128);
    float4 x3 = *(const float4*)(src + 192);
    float4 m;
    m.x = fmaf(w0, x0.x, fmaf(w1, x1.x, fmaf(w2, x2.x, w3 * x3.x)));
    m.y = fmaf(w0, x0.y, fmaf(w1, x1.y, fmaf(w2, x2.y, w3 * x3.y)));
    m.z = fmaf(w0, x0.z, fmaf(w1, x1.z, fmaf(w2, x2.z, w3 * x3.z)));
    m.w = fmaf(w0, x0.w, fmaf(w1, x1.w, fmaf(w2, x2.w, w3 * x3.w)));

    float* dst = g_acc + (size_t)d * OUT_CH + c0;
    asm volatile("red.global.add.v4.f32 [%0], {%1,%2,%3,%4};"
                 :: "l"(dst), "f"(m.x), "f"(m.y), "f"(m.z), "f"(m.w) : "memory");
}

// ---------------- k_final -----------------------------------------------------
__global__ void k_final(const float* __restrict__ bias, float* __restrict__ out) {
    int i = blockIdx.x * blockDim.x + threadIdx.x;
    if (i >= N_NODES * 16) return;
    int n = i >> 4;
    int c = (i & 15) * 4;
    float4 a = *(const float4*)(g_acc + (size_t)n * OUT_CH + c);
    float4 b = *(const float4*)(bias + c);
    float4 r = *(const float4*)(g_out + (size_t)n * BCOLS + 256 + c);
    float4 o;
    o.x = fmaxf(0.f, 0.25f * a.x + b.x + r.x);
    o.y = fmaxf(0.f, 0.25f * a.y + b.y + r.y);
    o.z = fmaxf(0.f, 0.25f * a.z + b.z + r.z);
    o.w = fmaxf(0.f, 0.25f * a.w + b.w + r.w);
    *(float4*)(out + (size_t)n * OUT_CH + c) = o;
}

// ---------------- launch ------------------------------------------------------
extern "C" void kernel_launch(void* const* d_in, const int* in_sizes, int n_in,
                              void* d_out, int out_size) {
    const float* x       = (const float*)d_in[0];
    const void*  ei      = d_in[1];
    const float* W       = (const float*)d_in[2];
    const float* att_src = (const float*)d_in[3];
    const float* att_dst = (const float*)d_in[4];
    const float* bias    = (const float*)d_in[5];
    const float* W_res   = (const float*)d_in[6];
    float* out = (float*)d_out;

    k_detect<<<1, 256>>>((const unsigned*)ei);
    k_prep<<<(MBLK * 4096 + 255) / 256, 256>>>(x);
    k_packB<<<(5 * 4096 + 255) / 256, 256>>>(W, W_res);
    k_init<<<1024, 256>>>();
    dim3 ggrid(5, MBLK);
    k_gemm<<<ggrid, 256>>>();
    k_logits<<<256, 256>>>(att_src, att_dst);
    k_sum<<<(EN_TOT + 255) / 256, 256>>>(ei);
    k_invden<<<(N_NODES * HEADS + 255) / 256, 256>>>();
    k_scatter<<<(int)(((long long)EN_TOT * 16 + 255) / 256), 256>>>(ei);
    k_final<<<(N_NODES * 16 + 255) / 256, 256>>>(bias, out);
}